// round 12
// baseline (speedup 1.0000x reference)
#include <cuda_runtime.h>
#include <cuda_bf16.h>
#include <cstdint>

// VQVAE nearest-codebook: single-pass bf16 mma.sync fast scores with
// provisional-threshold candidate BITMASK (no recompute pass) +
// warp-parallel exact fp32 rescore.
// z:[131072,64] f32, cb:[512,64] f32. out = (gather, gather).

#define Dm 64
#define Kc 512
#define ROWS_CTA 256
#define THREADS 512
#define MARGIN 2e-3f
#define QCAP 192

// ---- smem layout (bytes) ----
#define SM_ZBW  0                      // 256 x 36 u32 bf16x2(-2z), pitch 36      36864
#define SM_BSW  36864                  // 512 x 40 u32 codebook pairs (pitch 40)  81920
#define SM_MW   118784                 // 8 chunks x 512 tid u32 bit words        16384
#define SM_EEF  135168                 // 512 f32 exact ee                         2048
#define SM_ZZS  137216                 // 256 f32 exact zz                         1024
#define SM_MINR 138240                 // 256 u64 (score_bits<<32 | j)             2048
#define SM_QCNT 140288                 // 16 i32 (+pad)                             128
#define SM_QUE  140416                 // 16 x 192 u32 candidates                 12288
#define SM_TOTAL 152704

__device__ __forceinline__ void mma16816(float& c0, float& c1, float& c2, float& c3,
                                         unsigned a0, unsigned a1, unsigned a2, unsigned a3,
                                         unsigned b0, unsigned b1) {
    asm volatile("mma.sync.aligned.m16n8k16.row.col.f32.bf16.bf16.f32 "
                 "{%0,%1,%2,%3},{%4,%5,%6,%7},{%8,%9},{%0,%1,%2,%3};"
                 : "+f"(c0), "+f"(c1), "+f"(c2), "+f"(c3)
                 : "r"(a0), "r"(a1), "r"(a2), "r"(a3), "r"(b0), "r"(b1));
}

// Exact rescore (sequential fp32, matches reference rounding) + 64-bit atomicMin
// commit. key=(score_bits<<32)|j: scores >= 0 so bit order == value order;
// ties resolve to smallest j (first-index, as jnp.argmin).
__device__ __noinline__ void exact_commit(unsigned pk, const float* __restrict__ z,
                                          const float* __restrict__ cb, size_t blockRow,
                                          const float* zzs, const float* eef,
                                          unsigned long long* minr) {
    int row = pk & 255;
    int j = pk >> 8;
    const float4* zp = (const float4*)(z + (blockRow + row) * Dm);
    const float4* ep = (const float4*)(cb + (size_t)j * Dm);
    float dot = 0.0f;
#pragma unroll
    for (int i = 0; i < 16; ++i) {
        float4 a = __ldg(zp + i);
        float4 b = __ldg(ep + i);
        dot = __fmaf_rn(a.x, b.x, dot);
        dot = __fmaf_rn(a.y, b.y, dot);
        dot = __fmaf_rn(a.z, b.z, dot);
        dot = __fmaf_rn(a.w, b.w, dot);
    }
    float sx = __fadd_rn(__fadd_rn(zzs[row], eef[j]), __fmul_rn(-2.0f, dot));
    unsigned long long key = ((unsigned long long)__float_as_uint(sx) << 32) | (unsigned)j;
    atomicMin(minr + row, key);
}

__global__ void __launch_bounds__(THREADS, 1)
vq_kernel(const float* __restrict__ z, const float* __restrict__ cb,
          float* __restrict__ out, long long half) {
    extern __shared__ char sm[];
    unsigned* zbw = (unsigned*)(sm + SM_ZBW);
    unsigned* bsw = (unsigned*)(sm + SM_BSW);
    unsigned* mw = (unsigned*)(sm + SM_MW);
    float* eef = (float*)(sm + SM_EEF);
    float* zzs = (float*)(sm + SM_ZZS);
    unsigned long long* minr = (unsigned long long*)(sm + SM_MINR);
    int* qcnt = (int*)(sm + SM_QCNT);
    unsigned* que = (unsigned*)(sm + SM_QUE);

    const int tid = threadIdx.x, lane = tid & 31, wid = tid >> 5;
    const int q = lane & 3, rg = lane >> 2;
    const size_t blockRow = (size_t)blockIdx.x * ROWS_CTA;

    if (tid < 16) qcnt[tid] = 0;

    // ---------------- prolog ----------------
    if (tid < ROWS_CTA) {
        // z row -> exact zz + bf16(-2z) staged (pitch 36)
        minr[tid] = ~0ull;
        const float4* zr = (const float4*)(z + (blockRow + tid) * Dm);
        float4 v[16];
#pragma unroll
        for (int i = 0; i < 16; ++i) v[i] = zr[i];
        float zz = 0.0f;
#pragma unroll
        for (int i = 0; i < 16; ++i) {
            zz = __fadd_rn(zz, __fmul_rn(v[i].x, v[i].x));
            zz = __fadd_rn(zz, __fmul_rn(v[i].y, v[i].y));
            zz = __fadd_rn(zz, __fmul_rn(v[i].z, v[i].z));
            zz = __fadd_rn(zz, __fmul_rn(v[i].w, v[i].w));
        }
        zzs[tid] = zz;
        unsigned p[32];
#pragma unroll
        for (int i = 0; i < 16; ++i) {
            __nv_bfloat162 b0 = __float22bfloat162_rn(make_float2(-2.f * v[i].x, -2.f * v[i].y));
            __nv_bfloat162 b1 = __float22bfloat162_rn(make_float2(-2.f * v[i].z, -2.f * v[i].w));
            p[2 * i] = *(unsigned*)&b0;
            p[2 * i + 1] = *(unsigned*)&b1;
        }
        uint4* d4 = (uint4*)(zbw + tid * 36);
#pragma unroll
        for (int i = 0; i < 8; ++i) d4[i] = make_uint4(p[4 * i], p[4 * i + 1], p[4 * i + 2], p[4 * i + 3]);
    } else {
        // codebook rows 2*(tid-256), +1 -> exact ee + pair-permuted bf16 (pitch 40)
        // Pair perm (validated R6/R11): position p holds original bf16x2 word
        // w = (p&~7) + ((p>>1)&3) + 4*(p&1)  -> one LDS.64 per mma k-step.
#pragma unroll
        for (int rr = 0; rr < 2; ++rr) {
            int j = (tid - ROWS_CTA) * 2 + rr;
            const float4* er = (const float4*)(cb + (size_t)j * Dm);
            float4 ev[16];
#pragma unroll
            for (int i = 0; i < 16; ++i) ev[i] = er[i];
            float s = 0.0f;
#pragma unroll
            for (int i = 0; i < 16; ++i) {
                s = __fadd_rn(s, __fmul_rn(ev[i].x, ev[i].x));
                s = __fadd_rn(s, __fmul_rn(ev[i].y, ev[i].y));
                s = __fadd_rn(s, __fmul_rn(ev[i].z, ev[i].z));
                s = __fadd_rn(s, __fmul_rn(ev[i].w, ev[i].w));
            }
            eef[j] = s;
            unsigned pw[32];
#pragma unroll
            for (int p = 0; p < 32; ++p) {
                int w = (p & ~7) + ((p >> 1) & 3) + 4 * (p & 1);
                float4 f = ev[w >> 1];
                float lo = (w & 1) ? f.z : f.x;
                float hi = (w & 1) ? f.w : f.y;
                __nv_bfloat162 b = __float22bfloat162_rn(make_float2(lo, hi));
                pw[p] = *(unsigned*)&b;
            }
            uint4* d4 = (uint4*)(bsw + j * 40);
#pragma unroll
            for (int i = 0; i < 8; ++i) d4[i] = make_uint4(pw[4 * i], pw[4 * i + 1], pw[4 * i + 2], pw[4 * i + 3]);
        }
    }
    __syncthreads();

    // ---------------- A fragments: M=16 (rows ra, ra+8) ----------------
    const int ra = wid * 16 + rg;
    unsigned a[16];
#pragma unroll
    for (int ks = 0; ks < 4; ++ks) {
        int rbase = ra * 36;
        a[ks * 4 + 0] = zbw[rbase + q + ks * 8];
        a[ks * 4 + 1] = zbw[rbase + 8 * 36 + q + ks * 8];
        a[ks * 4 + 2] = zbw[rbase + q + 4 + ks * 8];
        a[ks * 4 + 3] = zbw[rbase + 8 * 36 + q + 4 + ks * 8];
    }
    const float2* ee2p = (const float2*)eef;

    // ---------------- bootstrap thresholds from tile 0 (no bits) ----------------
    float m0, m1;
    {
        float2 e2 = ee2p[q];
        float c0 = e2.x, c1 = e2.y, c2 = e2.x, c3 = e2.y;
        const unsigned* bp = bsw + rg * 40 + 2 * q;
#pragma unroll
        for (int ks = 0; ks < 4; ++ks) {
            uint2 b = *(const uint2*)(bp + ks * 8);
            mma16816(c0, c1, c2, c3, a[ks * 4], a[ks * 4 + 1], a[ks * 4 + 2], a[ks * 4 + 3], b.x, b.y);
        }
        m0 = fminf(c0, c1);
        m1 = fminf(c2, c3);
    }
    float r0 = m0, r1 = m1;
#pragma unroll
    for (int off = 1; off < 4; off <<= 1) {
        r0 = fminf(r0, __shfl_xor_sync(0xffffffffu, r0, off));
        r1 = fminf(r1, __shfl_xor_sync(0xffffffffu, r1, off));
    }
    float t0 = r0 + MARGIN, t1 = r1 + MARGIN;

    // ---------------- single pass: score + record candidate bits ----------------
    // Provisional thresholds (running min + MARGIN) only shrink -> bit set is a
    // superset of the final candidate set. Bits: chunk word, tile tt gets nibble
    // tt*4: bit0 c0(row ra, j), bit1 c1(ra, j+1), bit2 c2(ra+8, j), bit3 c3(ra+8, j+1).
#pragma unroll 1
    for (int ch = 0; ch < 8; ++ch) {
        unsigned mword = 0;
#pragma unroll
        for (int tt = 0; tt < 8; ++tt) {
            int t = ch * 8 + tt;
            float2 e2 = ee2p[t * 4 + q];
            float c0 = e2.x, c1 = e2.y, c2 = e2.x, c3 = e2.y;
            const unsigned* bp = bsw + (t * 8 + rg) * 40 + 2 * q;
#pragma unroll
            for (int ks = 0; ks < 4; ++ks) {
                uint2 b = *(const uint2*)(bp + ks * 8);
                mma16816(c0, c1, c2, c3, a[ks * 4], a[ks * 4 + 1], a[ks * 4 + 2], a[ks * 4 + 3], b.x, b.y);
            }
            m0 = fminf(m0, fminf(c0, c1));
            m1 = fminf(m1, fminf(c2, c3));
            unsigned bb = (c0 <= t0 ? 1u : 0u) | (c1 <= t0 ? 2u : 0u)
                        | (c2 <= t1 ? 4u : 0u) | (c3 <= t1 ? 8u : 0u);
            mword |= bb << (tt * 4);
        }
        mw[ch * THREADS + tid] = mword;
        // refresh provisional thresholds (monotone non-increasing)
        r0 = m0; r1 = m1;
#pragma unroll
        for (int off = 1; off < 4; off <<= 1) {
            r0 = fminf(r0, __shfl_xor_sync(0xffffffffu, r0, off));
            r1 = fminf(r1, __shfl_xor_sync(0xffffffffu, r1, off));
        }
        t0 = r0 + MARGIN;
        t1 = r1 + MARGIN;
    }

    // ---------------- walk bits, push candidates ----------------
#define PUSH(rowv, jv) do {                                                       \
        unsigned pk_ = (unsigned)(rowv) | ((unsigned)(jv) << 8);                  \
        int qi_ = atomicAdd(qcnt + wid, 1);                                       \
        if (qi_ < QCAP) que[wid * QCAP + qi_] = pk_;                              \
        else exact_commit(pk_, z, cb, blockRow, zzs, eef, minr);                  \
    } while (0)

#pragma unroll 1
    for (int ch = 0; ch < 8; ++ch) {
        unsigned m = mw[ch * THREADS + tid];
        while (m) {
            int b = __ffs(m) - 1;
            m &= m - 1;
            int tt = b >> 2, s = b & 3;
            int row = ra + ((s >> 1) << 3);
            int j = (ch * 8 + tt) * 8 + 2 * q + (s & 1);
            PUSH(row, j);
        }
    }
#undef PUSH

    // ---------------- drain: 32 lanes rescore distinct candidates ----------------
    __syncwarp();
    int n = *(volatile int*)(qcnt + wid);
    if (n > QCAP) n = QCAP;
    for (int base = 0; base < n; base += 32) {
        int k2 = base + lane;
        if (k2 < n) exact_commit(que[wid * QCAP + k2], z, cb, blockRow, zzs, eef, minr);
    }
    __syncthreads();

    // ---------------- gather + write both tuple halves ----------------
    {
        int row = tid >> 1, hh = tid & 1;
        int j = (int)(unsigned)(minr[row] & 0xFFFFFFFFull);
        size_t g = blockRow + row;
        const float4* s4 = (const float4*)(cb + (size_t)j * Dm + hh * 32);
        float4* o1 = (float4*)(out + g * Dm + hh * 32);
        float4* o2 = (half > 0) ? (float4*)(out + half + g * Dm + hh * 32) : nullptr;
#pragma unroll
        for (int i = 0; i < 8; ++i) {
            float4 tv = s4[i];
            o1[i] = tv;
            if (o2) o2[i] = tv;
        }
    }
}

extern "C" void kernel_launch(void* const* d_in, const int* in_sizes, int n_in,
                              void* d_out, int out_size) {
    const float* z = (const float*)d_in[0];
    const float* cb = (const float*)d_in[1];
    float* out = (float*)d_out;
    const int N = in_sizes[0] / Dm;                      // 131072
    long long half = ((long long)out_size >= 2LL * N * Dm) ? (long long)out_size / 2 : 0;

    cudaFuncSetAttribute(vq_kernel, cudaFuncAttributeMaxDynamicSharedMemorySize, SM_TOTAL);
    vq_kernel<<<N / ROWS_CTA, THREADS, SM_TOTAL>>>(z, cb, out, half);
}

// round 13
// speedup vs baseline: 1.2119x; 1.2119x over previous
#include <cuda_runtime.h>
#include <cuda_bf16.h>
#include <cstdint>

// VQVAE nearest-codebook: single-pass bf16 mma.sync fast scores (M=32/warp)
// with provisional-threshold candidate bitmask + warp-parallel exact fp32
// rescore. z:[131072,64] f32, cb:[512,64] f32. out = (gather, gather).

#define Dm 64
#define Kc 512
#define ROWS_CTA 512
#define THREADS 512
#define MARGIN 2e-3f
#define QCAP 256

// ---- smem layout (bytes) ----
#define SM_ZBW  0                      // 512 x 36 u32 bf16x2(-2z), pitch 36      73728
#define SM_BSW  73728                  // 512 x 40 u32 codebook pairs (pitch 40)  81920
#define SM_MW   155648                 // 16 chunks x 512 tid u32 bit words       32768
#define SM_EEF  188416                 // 512 f32 exact ee                         2048
#define SM_ZZS  190464                 // 512 f32 exact zz                         2048
#define SM_MINR 192512                 // 512 u64 (score_bits<<32 | j)             4096
#define SM_QCNT 196608                 // 16 i32 (+pad)                             128
#define SM_QUE  196736                 // 16 x 256 u32 candidates                 16384
#define SM_TOTAL 213120

__device__ __forceinline__ void mma16816(float& c0, float& c1, float& c2, float& c3,
                                         unsigned a0, unsigned a1, unsigned a2, unsigned a3,
                                         unsigned b0, unsigned b1) {
    asm volatile("mma.sync.aligned.m16n8k16.row.col.f32.bf16.bf16.f32 "
                 "{%0,%1,%2,%3},{%4,%5,%6,%7},{%8,%9},{%0,%1,%2,%3};"
                 : "+f"(c0), "+f"(c1), "+f"(c2), "+f"(c3)
                 : "r"(a0), "r"(a1), "r"(a2), "r"(a3), "r"(b0), "r"(b1));
}

// Exact rescore (sequential fp32, matches reference rounding) + 64-bit atomicMin
// commit. key=(score_bits<<32)|j: scores >= 0 so bit order == value order;
// ties resolve to smallest j (first-index, as jnp.argmin).
__device__ __noinline__ void exact_commit(unsigned pk, const float* __restrict__ z,
                                          const float* __restrict__ cb, size_t blockRow,
                                          const float* zzs, const float* eef,
                                          unsigned long long* minr) {
    int row = pk & 511;
    int j = pk >> 9;
    const float4* zp = (const float4*)(z + (blockRow + row) * Dm);
    const float4* ep = (const float4*)(cb + (size_t)j * Dm);
    float dot = 0.0f;
#pragma unroll
    for (int i = 0; i < 16; ++i) {
        float4 a = __ldg(zp + i);
        float4 b = __ldg(ep + i);
        dot = __fmaf_rn(a.x, b.x, dot);
        dot = __fmaf_rn(a.y, b.y, dot);
        dot = __fmaf_rn(a.z, b.z, dot);
        dot = __fmaf_rn(a.w, b.w, dot);
    }
    float sx = __fadd_rn(__fadd_rn(zzs[row], eef[j]), __fmul_rn(-2.0f, dot));
    unsigned long long key = ((unsigned long long)__float_as_uint(sx) << 32) | (unsigned)j;
    atomicMin(minr + row, key);
}

__global__ void __launch_bounds__(THREADS, 1)
vq_kernel(const float* __restrict__ z, const float* __restrict__ cb,
          float* __restrict__ out, long long half) {
    extern __shared__ char sm[];
    unsigned* zbw = (unsigned*)(sm + SM_ZBW);
    unsigned* bsw = (unsigned*)(sm + SM_BSW);
    unsigned* mw = (unsigned*)(sm + SM_MW);
    float* eef = (float*)(sm + SM_EEF);
    float* zzs = (float*)(sm + SM_ZZS);
    unsigned long long* minr = (unsigned long long*)(sm + SM_MINR);
    int* qcnt = (int*)(sm + SM_QCNT);
    unsigned* que = (unsigned*)(sm + SM_QUE);

    const int tid = threadIdx.x, lane = tid & 31, wid = tid >> 5;
    const int q = lane & 3, rg = lane >> 2;
    const size_t blockRow = (size_t)blockIdx.x * ROWS_CTA;

    if (tid < 16) qcnt[tid] = 0;
    minr[tid] = ~0ull;

    // ---------------- prolog A: z row tid -> exact zz + bf16(-2z), pitch 36 ----------------
    {
        const float4* zr = (const float4*)(z + (blockRow + tid) * Dm);
        float4 v[16];
#pragma unroll
        for (int i = 0; i < 16; ++i) v[i] = zr[i];
        float zz = 0.0f;
#pragma unroll
        for (int i = 0; i < 16; ++i) {
            zz = __fadd_rn(zz, __fmul_rn(v[i].x, v[i].x));
            zz = __fadd_rn(zz, __fmul_rn(v[i].y, v[i].y));
            zz = __fadd_rn(zz, __fmul_rn(v[i].z, v[i].z));
            zz = __fadd_rn(zz, __fmul_rn(v[i].w, v[i].w));
        }
        zzs[tid] = zz;
        unsigned p[32];
#pragma unroll
        for (int i = 0; i < 16; ++i) {
            __nv_bfloat162 b0 = __float22bfloat162_rn(make_float2(-2.f * v[i].x, -2.f * v[i].y));
            __nv_bfloat162 b1 = __float22bfloat162_rn(make_float2(-2.f * v[i].z, -2.f * v[i].w));
            p[2 * i] = *(unsigned*)&b0;
            p[2 * i + 1] = *(unsigned*)&b1;
        }
        uint4* d4 = (uint4*)(zbw + tid * 36);
#pragma unroll
        for (int i = 0; i < 8; ++i) d4[i] = make_uint4(p[4 * i], p[4 * i + 1], p[4 * i + 2], p[4 * i + 3]);
    }

    // ---------------- prolog B: codebook row tid -> exact ee + bf16 pairs ----------------
    // Pair perm (validated): position p holds original bf16x2 word
    // w = (p&~7) + ((p>>1)&3) + 4*(p&1) -> one LDS.64 per mma k-step.
    {
        const float4* er = (const float4*)(cb + (size_t)tid * Dm);
        float4 ev[16];
#pragma unroll
        for (int i = 0; i < 16; ++i) ev[i] = er[i];
        float s = 0.0f;
#pragma unroll
        for (int i = 0; i < 16; ++i) {
            s = __fadd_rn(s, __fmul_rn(ev[i].x, ev[i].x));
            s = __fadd_rn(s, __fmul_rn(ev[i].y, ev[i].y));
            s = __fadd_rn(s, __fmul_rn(ev[i].z, ev[i].z));
            s = __fadd_rn(s, __fmul_rn(ev[i].w, ev[i].w));
        }
        eef[tid] = s;
        unsigned pw[32];
#pragma unroll
        for (int p = 0; p < 32; ++p) {
            int w = (p & ~7) + ((p >> 1) & 3) + 4 * (p & 1);
            float4 f = ev[w >> 1];
            float lo = (w & 1) ? f.z : f.x;
            float hi = (w & 1) ? f.w : f.y;
            __nv_bfloat162 b = __float22bfloat162_rn(make_float2(lo, hi));
            pw[p] = *(unsigned*)&b;
        }
        uint4* d4 = (uint4*)(bsw + tid * 40);
#pragma unroll
        for (int i = 0; i < 8; ++i) d4[i] = make_uint4(pw[4 * i], pw[4 * i + 1], pw[4 * i + 2], pw[4 * i + 3]);
    }
    __syncthreads();

    // ---------------- A fragments: M=32 (rows ra, ra+8, ra+16, ra+24) ----------------
    const int ra = wid * 32 + rg;
    unsigned a[32];
#pragma unroll
    for (int b = 0; b < 2; ++b)
#pragma unroll
        for (int ks = 0; ks < 4; ++ks) {
            int rbase = (ra + 16 * b) * 36;
            a[b * 16 + ks * 4 + 0] = zbw[rbase + q + ks * 8];
            a[b * 16 + ks * 4 + 1] = zbw[rbase + 8 * 36 + q + ks * 8];
            a[b * 16 + ks * 4 + 2] = zbw[rbase + q + 4 + ks * 8];
            a[b * 16 + ks * 4 + 3] = zbw[rbase + 8 * 36 + q + 4 + ks * 8];
        }
    const float2* ee2p = (const float2*)eef;

    // ---------------- bootstrap thresholds from tile 0 (scored twice; no bits) --------
    float m0, m1, m2, m3;
    {
        float2 e2 = ee2p[q];
        float c0 = e2.x, c1 = e2.y, c2 = e2.x, c3 = e2.y;
        float c4 = e2.x, c5 = e2.y, c6 = e2.x, c7 = e2.y;
        const unsigned* bp = bsw + rg * 40 + 2 * q;
#pragma unroll
        for (int ks = 0; ks < 4; ++ks) {
            uint2 b = *(const uint2*)(bp + ks * 8);
            mma16816(c0, c1, c2, c3, a[ks * 4], a[ks * 4 + 1], a[ks * 4 + 2], a[ks * 4 + 3], b.x, b.y);
            mma16816(c4, c5, c6, c7, a[16 + ks * 4], a[17 + ks * 4], a[18 + ks * 4], a[19 + ks * 4], b.x, b.y);
        }
        m0 = fminf(c0, c1); m1 = fminf(c2, c3);
        m2 = fminf(c4, c5); m3 = fminf(c6, c7);
    }
    float r0 = m0, r1 = m1, r2 = m2, r3 = m3;
#pragma unroll
    for (int off = 1; off < 4; off <<= 1) {
        r0 = fminf(r0, __shfl_xor_sync(0xffffffffu, r0, off));
        r1 = fminf(r1, __shfl_xor_sync(0xffffffffu, r1, off));
        r2 = fminf(r2, __shfl_xor_sync(0xffffffffu, r2, off));
        r3 = fminf(r3, __shfl_xor_sync(0xffffffffu, r3, off));
    }
    float t0 = r0 + MARGIN, t1 = r1 + MARGIN, t2 = r2 + MARGIN, t3 = r3 + MARGIN;

    // ---------------- single pass: score + record candidate bits ----------------
    // Provisional thresholds (running min + MARGIN) only shrink -> recorded bit
    // set is a superset of the final candidate set; exact rescore decides.
    // Word per 4-tile chunk: bits [tt*8 + s], s: c0..c7 (rows ra+{0,0,8,8,16,16,24,24},
    // code j / j+1 alternating).
#pragma unroll 1
    for (int ch = 0; ch < 16; ++ch) {
        unsigned mword = 0;
#pragma unroll
        for (int tt = 0; tt < 4; ++tt) {
            int t = ch * 4 + tt;
            float2 e2 = ee2p[t * 4 + q];
            float c0 = e2.x, c1 = e2.y, c2 = e2.x, c3 = e2.y;
            float c4 = e2.x, c5 = e2.y, c6 = e2.x, c7 = e2.y;
            const unsigned* bp = bsw + (t * 8 + rg) * 40 + 2 * q;
#pragma unroll
            for (int ks = 0; ks < 4; ++ks) {
                uint2 b = *(const uint2*)(bp + ks * 8);
                mma16816(c0, c1, c2, c3, a[ks * 4], a[ks * 4 + 1], a[ks * 4 + 2], a[ks * 4 + 3], b.x, b.y);
                mma16816(c4, c5, c6, c7, a[16 + ks * 4], a[17 + ks * 4], a[18 + ks * 4], a[19 + ks * 4], b.x, b.y);
            }
            m0 = fminf(m0, fminf(c0, c1));
            m1 = fminf(m1, fminf(c2, c3));
            m2 = fminf(m2, fminf(c4, c5));
            m3 = fminf(m3, fminf(c6, c7));
            unsigned bb = (c0 <= t0 ? 1u : 0u) | (c1 <= t0 ? 2u : 0u)
                        | (c2 <= t1 ? 4u : 0u) | (c3 <= t1 ? 8u : 0u)
                        | (c4 <= t2 ? 16u : 0u) | (c5 <= t2 ? 32u : 0u)
                        | (c6 <= t3 ? 64u : 0u) | (c7 <= t3 ? 128u : 0u);
            mword |= bb << (tt * 8);
        }
        mw[ch * THREADS + tid] = mword;
        // refresh provisional thresholds (monotone non-increasing)
        r0 = m0; r1 = m1; r2 = m2; r3 = m3;
#pragma unroll
        for (int off = 1; off < 4; off <<= 1) {
            r0 = fminf(r0, __shfl_xor_sync(0xffffffffu, r0, off));
            r1 = fminf(r1, __shfl_xor_sync(0xffffffffu, r1, off));
            r2 = fminf(r2, __shfl_xor_sync(0xffffffffu, r2, off));
            r3 = fminf(r3, __shfl_xor_sync(0xffffffffu, r3, off));
        }
        t0 = r0 + MARGIN; t1 = r1 + MARGIN; t2 = r2 + MARGIN; t3 = r3 + MARGIN;
    }

    // ---------------- walk bits, push candidates ----------------
#define PUSH(rowv, jv) do {                                                       \
        unsigned pk_ = (unsigned)(rowv) | ((unsigned)(jv) << 9);                  \
        int qi_ = atomicAdd(qcnt + wid, 1);                                       \
        if (qi_ < QCAP) que[wid * QCAP + qi_] = pk_;                              \
        else exact_commit(pk_, z, cb, blockRow, zzs, eef, minr);                  \
    } while (0)

#pragma unroll 1
    for (int ch = 0; ch < 16; ++ch) {
        unsigned m = mw[ch * THREADS + tid];
        while (m) {
            int b = __ffs(m) - 1;
            m &= m - 1;
            int tt = b >> 3, s = b & 7;
            int row = ra + ((s >> 1) << 3);
            int j = (ch * 4 + tt) * 8 + 2 * q + (s & 1);
            PUSH(row, j);
        }
    }
#undef PUSH

    // ---------------- drain: 32 lanes rescore distinct candidates ----------------
    __syncwarp();
    int n = *(volatile int*)(qcnt + wid);
    if (n > QCAP) n = QCAP;
    for (int base = 0; base < n; base += 32) {
        int k2 = base + lane;
        if (k2 < n) exact_commit(que[wid * QCAP + k2], z, cb, blockRow, zzs, eef, minr);
    }
    __syncthreads();

    // ---------------- gather + write both tuple halves ----------------
#pragma unroll
    for (int it = 0; it < 2; ++it) {
        int row = (tid >> 1) + it * 256, hh = tid & 1;
        int j = (int)(unsigned)(minr[row] & 0xFFFFFFFFull);
        size_t g = blockRow + row;
        const float4* s4 = (const float4*)(cb + (size_t)j * Dm + hh * 32);
        float4* o1 = (float4*)(out + g * Dm + hh * 32);
        float4* o2 = (half > 0) ? (float4*)(out + half + g * Dm + hh * 32) : nullptr;
#pragma unroll
        for (int i = 0; i < 8; ++i) {
            float4 tv = s4[i];
            o1[i] = tv;
            if (o2) o2[i] = tv;
        }
    }
}

extern "C" void kernel_launch(void* const* d_in, const int* in_sizes, int n_in,
                              void* d_out, int out_size) {
    const float* z = (const float*)d_in[0];
    const float* cb = (const float*)d_in[1];
    float* out = (float*)d_out;
    const int N = in_sizes[0] / Dm;                      // 131072
    long long half = ((long long)out_size >= 2LL * N * Dm) ? (long long)out_size / 2 : 0;

    cudaFuncSetAttribute(vq_kernel, cudaFuncAttributeMaxDynamicSharedMemorySize, SM_TOTAL);
    vq_kernel<<<N / ROWS_CTA, THREADS, SM_TOTAL>>>(z, cb, out, half);
}

// round 14
// speedup vs baseline: 1.8674x; 1.5409x over previous
#include <cuda_runtime.h>
#include <cuda_fp16.h>
#include <cstdint>

// VQVAE nearest-codebook: fp16 mma.sync (f16 accum) fast scores + warp-parallel
// exact fp32 rescore. Single fused kernel.
// z:[131072,64] f32, cb:[512,64] f32. out = (gather, gather).

#define Dm 64
#define Kc 512
#define ROWS_CTA 512
#define THREADS 512
#define NTILES 64
#define MARGIN 2e-3f
#define QCAP 256

// ---- smem layout (bytes) ----
#define SM_ZHW  0                      // 512 x 36 u32 f16x2(-2z), pitch 36       73728
#define SM_BSW  73728                  // 512 x 40 u32 codebook pairs (pitch 40)  81920
#define SM_TMIN 155648                 // 16 warps x 64 tiles x 8 rg, fp16        16384
#define SM_EEF  172032                 // 512 f32 exact ee                         2048
#define SM_EEH  174080                 // 512 f16 ee (accumulator init)            1024
#define SM_ZZS  175104                 // 512 f32 exact zz                         2048
#define SM_MINR 177152                 // 512 u64 (score_bits<<32 | j)             4096
#define SM_QCNT 181248                 // 16 i32 (+pad)                             128
#define SM_QUE  181376                 // 16 x 256 u32 candidates                 16384
#define SM_TOTAL 197760

__device__ __forceinline__ void mma16816h(unsigned& c01, unsigned& c23,
                                          unsigned a0, unsigned a1, unsigned a2, unsigned a3,
                                          unsigned b0, unsigned b1) {
    asm volatile("mma.sync.aligned.m16n8k16.row.col.f16.f16.f16.f16 "
                 "{%0,%1},{%2,%3,%4,%5},{%6,%7},{%0,%1};"
                 : "+r"(c01), "+r"(c23)
                 : "r"(a0), "r"(a1), "r"(a2), "r"(a3), "r"(b0), "r"(b1));
}

__device__ __forceinline__ unsigned hmin2u(unsigned x, unsigned y) {
    __half2 r = __hmin2(*(__half2*)&x, *(__half2*)&y);
    return *(unsigned*)&r;
}

// Exact rescore (sequential fp32, matches reference rounding) + 64-bit atomicMin
// commit. key=(score_bits<<32)|j: scores >= 0 so bit order == value order;
// ties resolve to smallest j (first-index, as jnp.argmin).
__device__ __noinline__ void exact_commit(unsigned pk, const float* __restrict__ z,
                                          const float* __restrict__ cb, size_t blockRow,
                                          const float* zzs, const float* eef,
                                          unsigned long long* minr) {
    int row = pk & 511;
    int j = pk >> 9;
    const float4* zp = (const float4*)(z + (blockRow + row) * Dm);
    const float4* ep = (const float4*)(cb + (size_t)j * Dm);
    float dot = 0.0f;
#pragma unroll
    for (int i = 0; i < 16; ++i) {
        float4 a = __ldg(zp + i);
        float4 b = __ldg(ep + i);
        dot = __fmaf_rn(a.x, b.x, dot);
        dot = __fmaf_rn(a.y, b.y, dot);
        dot = __fmaf_rn(a.z, b.z, dot);
        dot = __fmaf_rn(a.w, b.w, dot);
    }
    float sx = __fadd_rn(__fadd_rn(zzs[row], eef[j]), __fmul_rn(-2.0f, dot));
    unsigned long long key = ((unsigned long long)__float_as_uint(sx) << 32) | (unsigned)j;
    atomicMin(minr + row, key);
}

__global__ void __launch_bounds__(THREADS, 1)
vq_kernel(const float* __restrict__ z, const float* __restrict__ cb,
          float* __restrict__ out, long long half) {
    extern __shared__ char sm[];
    unsigned* zhw = (unsigned*)(sm + SM_ZHW);
    unsigned* bsw = (unsigned*)(sm + SM_BSW);
    __half* tminp = (__half*)(sm + SM_TMIN);
    float* eef = (float*)(sm + SM_EEF);
    __half* eeh = (__half*)(sm + SM_EEH);
    float* zzs = (float*)(sm + SM_ZZS);
    unsigned long long* minr = (unsigned long long*)(sm + SM_MINR);
    int* qcnt = (int*)(sm + SM_QCNT);
    unsigned* que = (unsigned*)(sm + SM_QUE);

    const int tid = threadIdx.x, lane = tid & 31, wid = tid >> 5;
    const int q = lane & 3, rg = lane >> 2;
    const size_t blockRow = (size_t)blockIdx.x * ROWS_CTA;

    if (tid < 16) qcnt[tid] = 0;
    minr[tid] = ~0ull;

    // ---------------- prolog A: z row -> exact zz + f16(-2z), pitch 36 ----------------
    {
        const float4* zr = (const float4*)(z + (blockRow + tid) * Dm);
        float4 v[16];
#pragma unroll
        for (int i = 0; i < 16; ++i) v[i] = zr[i];
        float zz = 0.0f;
#pragma unroll
        for (int i = 0; i < 16; ++i) {
            zz = __fadd_rn(zz, __fmul_rn(v[i].x, v[i].x));
            zz = __fadd_rn(zz, __fmul_rn(v[i].y, v[i].y));
            zz = __fadd_rn(zz, __fmul_rn(v[i].z, v[i].z));
            zz = __fadd_rn(zz, __fmul_rn(v[i].w, v[i].w));
        }
        zzs[tid] = zz;
        unsigned p[32];
#pragma unroll
        for (int i = 0; i < 16; ++i) {
            __half2 b0 = __float22half2_rn(make_float2(-2.f * v[i].x, -2.f * v[i].y));
            __half2 b1 = __float22half2_rn(make_float2(-2.f * v[i].z, -2.f * v[i].w));
            p[2 * i] = *(unsigned*)&b0;
            p[2 * i + 1] = *(unsigned*)&b1;
        }
        uint4* d4 = (uint4*)(zhw + tid * 36);
#pragma unroll
        for (int i = 0; i < 8; ++i) d4[i] = make_uint4(p[4 * i], p[4 * i + 1], p[4 * i + 2], p[4 * i + 3]);
    }

    // ---------------- prolog B: codebook row tid -> exact ee + f16 pairs ----------------
    // Pair perm (validated): position p holds original f16x2 word
    // w = (p&~7) + ((p>>1)&3) + 4*(p&1) -> one LDS.64 per mma k-step.
    {
        const float4* er = (const float4*)(cb + (size_t)tid * Dm);
        float4 ev[16];
#pragma unroll
        for (int i = 0; i < 16; ++i) ev[i] = er[i];
        float s = 0.0f;
#pragma unroll
        for (int i = 0; i < 16; ++i) {
            s = __fadd_rn(s, __fmul_rn(ev[i].x, ev[i].x));
            s = __fadd_rn(s, __fmul_rn(ev[i].y, ev[i].y));
            s = __fadd_rn(s, __fmul_rn(ev[i].z, ev[i].z));
            s = __fadd_rn(s, __fmul_rn(ev[i].w, ev[i].w));
        }
        eef[tid] = s;
        eeh[tid] = __float2half_rn(s);
        unsigned pw[32];
#pragma unroll
        for (int p = 0; p < 32; ++p) {
            int w = (p & ~7) + ((p >> 1) & 3) + 4 * (p & 1);
            float4 f = ev[w >> 1];
            float lo = (w & 1) ? f.z : f.x;
            float hi = (w & 1) ? f.w : f.y;
            __half2 b = __float22half2_rn(make_float2(lo, hi));
            pw[p] = *(unsigned*)&b;
        }
        uint4* d4 = (uint4*)(bsw + tid * 40);
#pragma unroll
        for (int i = 0; i < 8; ++i) d4[i] = make_uint4(pw[4 * i], pw[4 * i + 1], pw[4 * i + 2], pw[4 * i + 3]);
    }
    __syncthreads();

    // ---------------- A fragments: M=32 (rows ra, ra+8, ra+16, ra+24) ----------------
    const int ra = wid * 32 + rg;
    unsigned a[32];
#pragma unroll
    for (int b = 0; b < 2; ++b)
#pragma unroll
        for (int ks = 0; ks < 4; ++ks) {
            int rbase = (ra + 16 * b) * 36;
            a[b * 16 + ks * 4 + 0] = zhw[rbase + q + ks * 8];
            a[b * 16 + ks * 4 + 1] = zhw[rbase + 8 * 36 + q + ks * 8];
            a[b * 16 + ks * 4 + 2] = zhw[rbase + q + 4 + ks * 8];
            a[b * 16 + ks * 4 + 3] = zhw[rbase + 8 * 36 + q + 4 + ks * 8];
        }
    const unsigned* eeh2 = (const unsigned*)eeh;   // half2 words: idx t*4+q -> codes (jb, jb+1)

    // ---------------- pass 1: fast mins (score = ee - 2 z.e, fp16) ----------------
    // c01: rows ra, cols (jb, jb+1) packed; c23: ra+8; c45: ra+16; c67: ra+24.
    unsigned mm0 = 0x7BFF7BFFu, mm1 = 0x7BFF7BFFu, mm2 = 0x7BFF7BFFu, mm3 = 0x7BFF7BFFu;
#pragma unroll 2
    for (int t = 0; t < NTILES; ++t) {
        unsigned einit = eeh2[t * 4 + q];
        unsigned c01 = einit, c23 = einit, c45 = einit, c67 = einit;
        const unsigned* bp = bsw + (t * 8 + rg) * 40 + 2 * q;
#pragma unroll
        for (int ks = 0; ks < 4; ++ks) {
            uint2 b = *(const uint2*)(bp + ks * 8);
            mma16816h(c01, c23, a[ks * 4], a[ks * 4 + 1], a[ks * 4 + 2], a[ks * 4 + 3], b.x, b.y);
            mma16816h(c45, c67, a[16 + ks * 4], a[17 + ks * 4], a[18 + ks * 4], a[19 + ks * 4], b.x, b.y);
        }
        mm0 = hmin2u(mm0, c01);
        mm1 = hmin2u(mm1, c23);
        mm2 = hmin2u(mm2, c45);
        mm3 = hmin2u(mm3, c67);
        unsigned tw = hmin2u(hmin2u(c01, c23), hmin2u(c45, c67));
        __half2 th = *(__half2*)&tw;
        float tm = fminf(__low2float(th), __high2float(th));
        tm = fminf(tm, __shfl_xor_sync(0xffffffffu, tm, 1));
        tm = fminf(tm, __shfl_xor_sync(0xffffffffu, tm, 2));
        if (q == 0) tminp[(wid * NTILES + t) * 8 + rg] = __float2half(tm);
    }
    __syncwarp();

    __half2 h0 = *(__half2*)&mm0, h1 = *(__half2*)&mm1;
    __half2 h2 = *(__half2*)&mm2, h3 = *(__half2*)&mm3;
    float mr0 = fminf(__low2float(h0), __high2float(h0));
    float mr1 = fminf(__low2float(h1), __high2float(h1));
    float mr2 = fminf(__low2float(h2), __high2float(h2));
    float mr3 = fminf(__low2float(h3), __high2float(h3));
#pragma unroll
    for (int off = 1; off < 4; off <<= 1) {
        mr0 = fminf(mr0, __shfl_xor_sync(0xffffffffu, mr0, off));
        mr1 = fminf(mr1, __shfl_xor_sync(0xffffffffu, mr1, off));
        mr2 = fminf(mr2, __shfl_xor_sync(0xffffffffu, mr2, off));
        mr3 = fminf(mr3, __shfl_xor_sync(0xffffffffu, mr3, off));
    }
    const float t0 = mr0 + MARGIN, t1 = mr1 + MARGIN;
    const float t2 = mr2 + MARGIN, t3 = mr3 + MARGIN;
    const float thrq = fmaxf(fmaxf(t0, t1), fmaxf(t2, t3));   // tminp is lossless fp16

    // ---------------- pass 2: pruned recompute, enqueue candidates ----------------
#define PUSH(rowv, jv) do {                                                       \
        unsigned pk_ = (unsigned)(rowv) | ((unsigned)(jv) << 9);                  \
        int qi_ = atomicAdd(qcnt + wid, 1);                                       \
        if (qi_ < QCAP) que[wid * QCAP + qi_] = pk_;                              \
        else exact_commit(pk_, z, cb, blockRow, zzs, eef, minr);                  \
    } while (0)

#pragma unroll 1
    for (int t = 0; t < NTILES; ++t) {
        float tm = __half2float(tminp[(wid * NTILES + t) * 8 + rg]);
        if (!__any_sync(0xffffffffu, tm <= thrq)) continue;

        unsigned einit = eeh2[t * 4 + q];
        unsigned c01 = einit, c23 = einit, c45 = einit, c67 = einit;
        const unsigned* bp = bsw + (t * 8 + rg) * 40 + 2 * q;
#pragma unroll
        for (int ks = 0; ks < 4; ++ks) {
            uint2 b = *(const uint2*)(bp + ks * 8);
            mma16816h(c01, c23, a[ks * 4], a[ks * 4 + 1], a[ks * 4 + 2], a[ks * 4 + 3], b.x, b.y);
            mma16816h(c45, c67, a[16 + ks * 4], a[17 + ks * 4], a[18 + ks * 4], a[19 + ks * 4], b.x, b.y);
        }
        __half2 p0 = *(__half2*)&c01, p1 = *(__half2*)&c23;
        __half2 p2 = *(__half2*)&c45, p3 = *(__half2*)&c67;
        int jb = t * 8 + 2 * q;
        if (__low2float(p0) <= t0) PUSH(ra, jb);
        if (__high2float(p0) <= t0) PUSH(ra, jb + 1);
        if (__low2float(p1) <= t1) PUSH(ra + 8, jb);
        if (__high2float(p1) <= t1) PUSH(ra + 8, jb + 1);
        if (__low2float(p2) <= t2) PUSH(ra + 16, jb);
        if (__high2float(p2) <= t2) PUSH(ra + 16, jb + 1);
        if (__low2float(p3) <= t3) PUSH(ra + 24, jb);
        if (__high2float(p3) <= t3) PUSH(ra + 24, jb + 1);
    }
#undef PUSH

    // ---------------- drain queue: 32 lanes rescore distinct candidates ----------------
    __syncwarp();
    int n = *(volatile int*)(qcnt + wid);
    if (n > QCAP) n = QCAP;
    for (int base = 0; base < n; base += 32) {
        int k2 = base + lane;
        if (k2 < n) exact_commit(que[wid * QCAP + k2], z, cb, blockRow, zzs, eef, minr);
    }
    __syncthreads();

    // ---------------- gather + write both tuple halves ----------------
#pragma unroll
    for (int it = 0; it < 2; ++it) {
        int row = (tid >> 1) + it * 256, hh = tid & 1;
        int j = (int)(unsigned)(minr[row] & 0xFFFFFFFFull);
        size_t g = blockRow + row;
        const float4* s4 = (const float4*)(cb + (size_t)j * Dm + hh * 32);
        float4* o1 = (float4*)(out + g * Dm + hh * 32);
        float4* o2 = (half > 0) ? (float4*)(out + half + g * Dm + hh * 32) : nullptr;
#pragma unroll
        for (int i = 0; i < 8; ++i) {
            float4 tv = s4[i];
            o1[i] = tv;
            if (o2) o2[i] = tv;
        }
    }
}

extern "C" void kernel_launch(void* const* d_in, const int* in_sizes, int n_in,
                              void* d_out, int out_size) {
    const float* z = (const float*)d_in[0];
    const float* cb = (const float*)d_in[1];
    float* out = (float*)d_out;
    const int N = in_sizes[0] / Dm;                      // 131072
    long long half = ((long long)out_size >= 2LL * N * Dm) ? (long long)out_size / 2 : 0;

    cudaFuncSetAttribute(vq_kernel, cudaFuncAttributeMaxDynamicSharedMemorySize, SM_TOTAL);
    vq_kernel<<<N / ROWS_CTA, THREADS, SM_TOTAL>>>(z, cb, out, half);
}

// round 15
// speedup vs baseline: 1.9792x; 1.0599x over previous
#include <cuda_runtime.h>
#include <cuda_fp16.h>
#include <cstdint>

// VQVAE nearest-codebook: fp16 mma.sync (f16 accum) fast scores + warp-parallel
// exact fp32 rescore. Call-free hot loops (queue overflow -> global STG).
// z:[131072,64] f32, cb:[512,64] f32. out = (gather, gather).

#define Dm 64
#define Kc 512
#define ROWS_CTA 512
#define THREADS 512
#define NTILES 64
#define MARGIN 2e-3f
#define QCAP 256
#define OCAP 1024
#define NCTAS 256

__device__ unsigned g_ovf[NCTAS * 16 * OCAP];   // queue overflow spill (never hit in practice)

// ---- smem layout (bytes) ----
#define SM_ZHW  0                      // 512 x 36 u32 f16x2(-2z), pitch 36       73728
#define SM_BSW  73728                  // 512 x 40 u32 codebook pairs (pitch 40)  81920
#define SM_TMIN 155648                 // 16 warps x 64 tiles x 8 rg, fp16        16384
#define SM_EEF  172032                 // 512 f32 exact ee                         2048
#define SM_EEH  174080                 // 512 f16 ee (accumulator init)            1024
#define SM_ZZS  175104                 // 512 f32 exact zz                         2048
#define SM_MINR 177152                 // 512 u64 (score_bits<<32 | j)             4096
#define SM_QCNT 181248                 // 16 i32 (+pad)                             128
#define SM_QUE  181376                 // 16 x 256 u32 candidates                 16384
#define SM_TOTAL 197760

__device__ __forceinline__ void mma16816h(unsigned& c01, unsigned& c23,
                                          unsigned a0, unsigned a1, unsigned a2, unsigned a3,
                                          unsigned b0, unsigned b1) {
    asm volatile("mma.sync.aligned.m16n8k16.row.col.f16.f16.f16.f16 "
                 "{%0,%1},{%2,%3,%4,%5},{%6,%7},{%0,%1};"
                 : "+r"(c01), "+r"(c23)
                 : "r"(a0), "r"(a1), "r"(a2), "r"(a3), "r"(b0), "r"(b1));
}

__device__ __forceinline__ unsigned hmin2u(unsigned x, unsigned y) {
    __half2 r = __hmin2(*(__half2*)&x, *(__half2*)&y);
    return *(unsigned*)&r;
}

// Exact rescore (sequential fp32, matches reference rounding) + 64-bit atomicMin
// commit. key=(score_bits<<32)|j: scores >= 0 so bit order == value order;
// ties resolve to smallest j (first-index, as jnp.argmin).
// Called ONLY after the mainloop (drain / fallback) - no hot-loop ABI pressure.
__device__ __noinline__ void exact_commit(unsigned pk, const float* __restrict__ z,
                                          const float* __restrict__ cb, size_t blockRow,
                                          const float* zzs, const float* eef,
                                          unsigned long long* minr) {
    int row = pk & 511;
    int j = pk >> 9;
    const float4* zp = (const float4*)(z + (blockRow + row) * Dm);
    const float4* ep = (const float4*)(cb + (size_t)j * Dm);
    float dot = 0.0f;
#pragma unroll
    for (int i = 0; i < 16; ++i) {
        float4 a = __ldg(zp + i);
        float4 b = __ldg(ep + i);
        dot = __fmaf_rn(a.x, b.x, dot);
        dot = __fmaf_rn(a.y, b.y, dot);
        dot = __fmaf_rn(a.z, b.z, dot);
        dot = __fmaf_rn(a.w, b.w, dot);
    }
    float sx = __fadd_rn(__fadd_rn(zzs[row], eef[j]), __fmul_rn(-2.0f, dot));
    unsigned long long key = ((unsigned long long)__float_as_uint(sx) << 32) | (unsigned)j;
    atomicMin(minr + row, key);
}

__global__ void __launch_bounds__(THREADS, 1)
vq_kernel(const float* __restrict__ z, const float* __restrict__ cb,
          float* __restrict__ out, long long half) {
    extern __shared__ char sm[];
    unsigned* zhw = (unsigned*)(sm + SM_ZHW);
    unsigned* bsw = (unsigned*)(sm + SM_BSW);
    __half* tminp = (__half*)(sm + SM_TMIN);
    float* eef = (float*)(sm + SM_EEF);
    __half* eeh = (__half*)(sm + SM_EEH);
    float* zzs = (float*)(sm + SM_ZZS);
    unsigned long long* minr = (unsigned long long*)(sm + SM_MINR);
    int* qcnt = (int*)(sm + SM_QCNT);
    unsigned* que = (unsigned*)(sm + SM_QUE);

    const int tid = threadIdx.x, lane = tid & 31, wid = tid >> 5;
    const int q = lane & 3, rg = lane >> 2;
    const size_t blockRow = (size_t)blockIdx.x * ROWS_CTA;

    if (tid < 16) qcnt[tid] = 0;
    minr[tid] = ~0ull;

    // ---------------- prolog A: z row -> exact zz + f16(-2z), chunked (reg diet) ----------
    {
        const float4* zr = (const float4*)(z + (blockRow + tid) * Dm);
        float zz = 0.0f;
#pragma unroll
        for (int c = 0; c < 2; ++c) {
            float4 v[8];
#pragma unroll
            for (int i = 0; i < 8; ++i) v[i] = zr[c * 8 + i];
#pragma unroll
            for (int i = 0; i < 8; ++i) {
                zz = __fadd_rn(zz, __fmul_rn(v[i].x, v[i].x));
                zz = __fadd_rn(zz, __fmul_rn(v[i].y, v[i].y));
                zz = __fadd_rn(zz, __fmul_rn(v[i].z, v[i].z));
                zz = __fadd_rn(zz, __fmul_rn(v[i].w, v[i].w));
            }
            unsigned p[16];
#pragma unroll
            for (int i = 0; i < 8; ++i) {
                __half2 b0 = __float22half2_rn(make_float2(-2.f * v[i].x, -2.f * v[i].y));
                __half2 b1 = __float22half2_rn(make_float2(-2.f * v[i].z, -2.f * v[i].w));
                p[2 * i] = *(unsigned*)&b0;
                p[2 * i + 1] = *(unsigned*)&b1;
            }
            uint4* d4 = (uint4*)(zhw + tid * 36) + c * 4;
#pragma unroll
            for (int i = 0; i < 4; ++i) d4[i] = make_uint4(p[4 * i], p[4 * i + 1], p[4 * i + 2], p[4 * i + 3]);
        }
        zzs[tid] = zz;
    }

    // ---------------- prolog B: codebook row tid -> exact ee + f16 pairs, chunked --------
    // Pair perm (validated): position p holds original f16x2 word
    // w = (p&~7) + ((p>>1)&3) + 4*(p&1); perm stays within 8-word blocks, so
    // chunk c covers p in [16c,16c+16) using only ev rows [8c,8c+8).
    {
        const float4* er = (const float4*)(cb + (size_t)tid * Dm);
        float s = 0.0f;
#pragma unroll
        for (int c = 0; c < 2; ++c) {
            float4 ev[8];
#pragma unroll
            for (int i = 0; i < 8; ++i) ev[i] = er[c * 8 + i];
#pragma unroll
            for (int i = 0; i < 8; ++i) {
                s = __fadd_rn(s, __fmul_rn(ev[i].x, ev[i].x));
                s = __fadd_rn(s, __fmul_rn(ev[i].y, ev[i].y));
                s = __fadd_rn(s, __fmul_rn(ev[i].z, ev[i].z));
                s = __fadd_rn(s, __fmul_rn(ev[i].w, ev[i].w));
            }
            unsigned pw[16];
#pragma unroll
            for (int pp = 0; pp < 16; ++pp) {
                int p = c * 16 + pp;
                int w = (p & ~7) + ((p >> 1) & 3) + 4 * (p & 1);
                float4 f = ev[(w >> 1) - c * 8];
                float lo = (w & 1) ? f.z : f.x;
                float hi = (w & 1) ? f.w : f.y;
                __half2 b = __float22half2_rn(make_float2(lo, hi));
                pw[pp] = *(unsigned*)&b;
            }
            uint4* d4 = (uint4*)(bsw + tid * 40) + c * 4;
#pragma unroll
            for (int i = 0; i < 4; ++i) d4[i] = make_uint4(pw[4 * i], pw[4 * i + 1], pw[4 * i + 2], pw[4 * i + 3]);
        }
        eef[tid] = s;
        eeh[tid] = __float2half_rn(s);
    }
    __syncthreads();

    // ---------------- A fragments: M=32 (rows ra, ra+8, ra+16, ra+24) ----------------
    const int ra = wid * 32 + rg;
    unsigned a[32];
#pragma unroll
    for (int b = 0; b < 2; ++b)
#pragma unroll
        for (int ks = 0; ks < 4; ++ks) {
            int rbase = (ra + 16 * b) * 36;
            a[b * 16 + ks * 4 + 0] = zhw[rbase + q + ks * 8];
            a[b * 16 + ks * 4 + 1] = zhw[rbase + 8 * 36 + q + ks * 8];
            a[b * 16 + ks * 4 + 2] = zhw[rbase + q + 4 + ks * 8];
            a[b * 16 + ks * 4 + 3] = zhw[rbase + 8 * 36 + q + 4 + ks * 8];
        }
    const unsigned* eeh2 = (const unsigned*)eeh;   // half2 words: idx t*4+q -> codes (jb, jb+1)

    // ---------------- pass 1: fast mins (score = ee - 2 z.e, fp16) ----------------
    unsigned mm0 = 0x7BFF7BFFu, mm1 = 0x7BFF7BFFu, mm2 = 0x7BFF7BFFu, mm3 = 0x7BFF7BFFu;
#pragma unroll 2
    for (int t = 0; t < NTILES; ++t) {
        unsigned einit = eeh2[t * 4 + q];
        unsigned c01 = einit, c23 = einit, c45 = einit, c67 = einit;
        const unsigned* bp = bsw + (t * 8 + rg) * 40 + 2 * q;
#pragma unroll
        for (int ks = 0; ks < 4; ++ks) {
            uint2 b = *(const uint2*)(bp + ks * 8);
            mma16816h(c01, c23, a[ks * 4], a[ks * 4 + 1], a[ks * 4 + 2], a[ks * 4 + 3], b.x, b.y);
            mma16816h(c45, c67, a[16 + ks * 4], a[17 + ks * 4], a[18 + ks * 4], a[19 + ks * 4], b.x, b.y);
        }
        mm0 = hmin2u(mm0, c01);
        mm1 = hmin2u(mm1, c23);
        mm2 = hmin2u(mm2, c45);
        mm3 = hmin2u(mm3, c67);
        unsigned tw = hmin2u(hmin2u(c01, c23), hmin2u(c45, c67));
        __half2 th = *(__half2*)&tw;
        float tm = fminf(__low2float(th), __high2float(th));
        tm = fminf(tm, __shfl_xor_sync(0xffffffffu, tm, 1));
        tm = fminf(tm, __shfl_xor_sync(0xffffffffu, tm, 2));
        if (q == 0) tminp[(wid * NTILES + t) * 8 + rg] = __float2half(tm);
    }
    __syncwarp();

    __half2 h0 = *(__half2*)&mm0, h1 = *(__half2*)&mm1;
    __half2 h2 = *(__half2*)&mm2, h3 = *(__half2*)&mm3;
    float mr0 = fminf(__low2float(h0), __high2float(h0));
    float mr1 = fminf(__low2float(h1), __high2float(h1));
    float mr2 = fminf(__low2float(h2), __high2float(h2));
    float mr3 = fminf(__low2float(h3), __high2float(h3));
#pragma unroll
    for (int off = 1; off < 4; off <<= 1) {
        mr0 = fminf(mr0, __shfl_xor_sync(0xffffffffu, mr0, off));
        mr1 = fminf(mr1, __shfl_xor_sync(0xffffffffu, mr1, off));
        mr2 = fminf(mr2, __shfl_xor_sync(0xffffffffu, mr2, off));
        mr3 = fminf(mr3, __shfl_xor_sync(0xffffffffu, mr3, off));
    }
    const float t0 = mr0 + MARGIN, t1 = mr1 + MARGIN;
    const float t2 = mr2 + MARGIN, t3 = mr3 + MARGIN;
    const float thrq = fmaxf(fmaxf(t0, t1), fmaxf(t2, t3));   // tminp is lossless fp16

    // ---------------- pass 2: pruned recompute, enqueue candidates (CALL-FREE) --------
    unsigned* ovf = g_ovf + ((size_t)blockIdx.x * 16 + wid) * OCAP;
#define PUSH(rowv, jv) do {                                                       \
        unsigned pk_ = (unsigned)(rowv) | ((unsigned)(jv) << 9);                  \
        int qi_ = atomicAdd(qcnt + wid, 1);                                       \
        if (qi_ < QCAP) que[wid * QCAP + qi_] = pk_;                              \
        else if (qi_ < QCAP + OCAP) ovf[qi_ - QCAP] = pk_;                        \
    } while (0)

#pragma unroll 1
    for (int t = 0; t < NTILES; ++t) {
        float tm = __half2float(tminp[(wid * NTILES + t) * 8 + rg]);
        if (!__any_sync(0xffffffffu, tm <= thrq)) continue;

        unsigned einit = eeh2[t * 4 + q];
        unsigned c01 = einit, c23 = einit, c45 = einit, c67 = einit;
        const unsigned* bp = bsw + (t * 8 + rg) * 40 + 2 * q;
#pragma unroll
        for (int ks = 0; ks < 4; ++ks) {
            uint2 b = *(const uint2*)(bp + ks * 8);
            mma16816h(c01, c23, a[ks * 4], a[ks * 4 + 1], a[ks * 4 + 2], a[ks * 4 + 3], b.x, b.y);
            mma16816h(c45, c67, a[16 + ks * 4], a[17 + ks * 4], a[18 + ks * 4], a[19 + ks * 4], b.x, b.y);
        }
        __half2 p0 = *(__half2*)&c01, p1 = *(__half2*)&c23;
        __half2 p2 = *(__half2*)&c45, p3 = *(__half2*)&c67;
        int jb = t * 8 + 2 * q;
        if (__low2float(p0) <= t0) PUSH(ra, jb);
        if (__high2float(p0) <= t0) PUSH(ra, jb + 1);
        if (__low2float(p1) <= t1) PUSH(ra + 8, jb);
        if (__high2float(p1) <= t1) PUSH(ra + 8, jb + 1);
        if (__low2float(p2) <= t2) PUSH(ra + 16, jb);
        if (__high2float(p2) <= t2) PUSH(ra + 16, jb + 1);
        if (__low2float(p3) <= t3) PUSH(ra + 24, jb);
        if (__high2float(p3) <= t3) PUSH(ra + 24, jb + 1);
    }
#undef PUSH

    // ---------------- drain: 32 lanes rescore distinct candidates ----------------
    __syncwarp();
    int n = *(volatile int*)(qcnt + wid);
    int ncap = n < (QCAP + OCAP) ? n : (QCAP + OCAP);
    for (int base = 0; base < ncap; base += 32) {
        int k2 = base + lane;
        if (k2 < ncap) {
            unsigned pk = (k2 < QCAP) ? que[wid * QCAP + k2] : ovf[k2 - QCAP];
            exact_commit(pk, z, cb, blockRow, zzs, eef, minr);
        }
    }
    if (n > QCAP + OCAP) {
        // Unreachable in practice; provably-correct fallback: exhaustive rescore
        // of this warp's 32 rows against all codes.
        for (int rr = 0; rr < 32; ++rr) {
            int row = wid * 32 + rr;
            for (int j = lane; j < Kc; j += 32)
                exact_commit((unsigned)row | ((unsigned)j << 9), z, cb, blockRow, zzs, eef, minr);
        }
    }
    __syncthreads();

    // ---------------- gather + write both tuple halves ----------------
#pragma unroll
    for (int it = 0; it < 2; ++it) {
        int row = (tid >> 1) + it * 256, hh = tid & 1;
        int j = (int)(unsigned)(minr[row] & 0xFFFFFFFFull);
        size_t g = blockRow + row;
        const float4* s4 = (const float4*)(cb + (size_t)j * Dm + hh * 32);
        float4* o1 = (float4*)(out + g * Dm + hh * 32);
        float4* o2 = (half > 0) ? (float4*)(out + half + g * Dm + hh * 32) : nullptr;
#pragma unroll
        for (int i = 0; i < 8; ++i) {
            float4 tv = s4[i];
            o1[i] = tv;
            if (o2) o2[i] = tv;
        }
    }
}

extern "C" void kernel_launch(void* const* d_in, const int* in_sizes, int n_in,
                              void* d_out, int out_size) {
    const float* z = (const float*)d_in[0];
    const float* cb = (const float*)d_in[1];
    float* out = (float*)d_out;
    const int N = in_sizes[0] / Dm;                      // 131072
    long long half = ((long long)out_size >= 2LL * N * Dm) ? (long long)out_size / 2 : 0;

    cudaFuncSetAttribute(vq_kernel, cudaFuncAttributeMaxDynamicSharedMemorySize, SM_TOTAL);
    vq_kernel<<<N / ROWS_CTA, THREADS, SM_TOTAL>>>(z, cb, out, half);
}

// round 16
// speedup vs baseline: 2.0368x; 1.0291x over previous
#include <cuda_runtime.h>
#include <cuda_fp16.h>
#include <cstdint>

// VQVAE nearest-codebook: fp16 mma.sync fast scores + warp-parallel exact fp32
// rescore. Persistent CTAs: codebook staged once, row-blocks looped.
// z:[131072,64] f32, cb:[512,64] f32. out = (gather, gather).

#define Dm 64
#define Kc 512
#define ROWS_CTA 512
#define THREADS 512
#define NTILES 64
#define MARGIN 2e-3f
#define QCAP 256
#define GRID 152

// ---- smem layout (bytes) ----
#define SM_ZHW  0                      // 512 x 36 u32 f16x2(-2z), pitch 36       73728
#define SM_BSW  73728                  // 512 x 40 u32 codebook pairs (pitch 40)  81920
#define SM_TMIN 155648                 // 16 warps x 64 tiles x 8 rg, fp16        16384
#define SM_EEF  172032                 // 512 f32 exact ee                         2048
#define SM_EEH  174080                 // 512 f16 ee (accumulator init)            1024
#define SM_ZZS  175104                 // 512 f32 exact zz                         2048
#define SM_MINR 177152                 // 512 u64 (score_bits<<32 | j)             4096
#define SM_QCNT 181248                 // 16 i32 (+pad)                             128
#define SM_WFLG 181376                 // 16 i32 overflow flags                     128
#define SM_QUE  181504                 // 16 x 256 u32 candidates                 16384
#define SM_TOTAL 197888

__device__ __forceinline__ void mma16816h(unsigned& c01, unsigned& c23,
                                          unsigned a0, unsigned a1, unsigned a2, unsigned a3,
                                          unsigned b0, unsigned b1) {
    asm volatile("mma.sync.aligned.m16n8k16.row.col.f16.f16.f16.f16 "
                 "{%0,%1},{%2,%3,%4,%5},{%6,%7},{%0,%1};"
                 : "+r"(c01), "+r"(c23)
                 : "r"(a0), "r"(a1), "r"(a2), "r"(a3), "r"(b0), "r"(b1));
}

__device__ __forceinline__ unsigned hmin2u(unsigned x, unsigned y) {
    __half2 r = __hmin2(*(__half2*)&x, *(__half2*)&y);
    return *(unsigned*)&r;
}

// Exact rescore (sequential fp32, matches reference rounding) + 64-bit atomicMin
// commit. key=(score_bits<<32)|j: scores >= 0 so bit order == value order;
// ties resolve to smallest j (first-index, as jnp.argmin).
// Called ONLY outside the mainloop (drain / fallback).
__device__ __noinline__ void exact_commit(unsigned pk, const float* __restrict__ z,
                                          const float* __restrict__ cb, size_t blockRow,
                                          const float* zzs, const float* eef,
                                          unsigned long long* minr) {
    int row = pk & 511;
    int j = pk >> 9;
    const float4* zp = (const float4*)(z + (blockRow + row) * Dm);
    const float4* ep = (const float4*)(cb + (size_t)j * Dm);
    float dot = 0.0f;
#pragma unroll
    for (int i = 0; i < 16; ++i) {
        float4 a = __ldg(zp + i);
        float4 b = __ldg(ep + i);
        dot = __fmaf_rn(a.x, b.x, dot);
        dot = __fmaf_rn(a.y, b.y, dot);
        dot = __fmaf_rn(a.z, b.z, dot);
        dot = __fmaf_rn(a.w, b.w, dot);
    }
    float sx = __fadd_rn(__fadd_rn(zzs[row], eef[j]), __fmul_rn(-2.0f, dot));
    unsigned long long key = ((unsigned long long)__float_as_uint(sx) << 32) | (unsigned)j;
    atomicMin(minr + row, key);
}

__global__ void __launch_bounds__(THREADS, 1)
vq_kernel(const float* __restrict__ z, const float* __restrict__ cb,
          float* __restrict__ out, long long half, int nblk) {
    extern __shared__ char sm[];
    unsigned* zhw = (unsigned*)(sm + SM_ZHW);
    unsigned* bsw = (unsigned*)(sm + SM_BSW);
    __half* tminp = (__half*)(sm + SM_TMIN);
    float* eef = (float*)(sm + SM_EEF);
    __half* eeh = (__half*)(sm + SM_EEH);
    float* zzs = (float*)(sm + SM_ZZS);
    unsigned long long* minr = (unsigned long long*)(sm + SM_MINR);
    int* qcnt = (int*)(sm + SM_QCNT);
    int* wflg = (int*)(sm + SM_WFLG);
    unsigned* que = (unsigned*)(sm + SM_QUE);

    const int tid = threadIdx.x, lane = tid & 31, wid = tid >> 5;
    const int q = lane & 3, rg = lane >> 2;

    // ---------------- prolog B (ONCE): codebook row tid -> exact ee + f16 pairs ----------
    // Pair perm (validated): position p holds original f16x2 word
    // w = (p&~7) + ((p>>1)&3) + 4*(p&1); perm stays within 8-word blocks.
    {
        const float4* er = (const float4*)(cb + (size_t)tid * Dm);
        float s = 0.0f;
#pragma unroll
        for (int c = 0; c < 2; ++c) {
            float4 ev[8];
#pragma unroll
            for (int i = 0; i < 8; ++i) ev[i] = er[c * 8 + i];
#pragma unroll
            for (int i = 0; i < 8; ++i) {
                s = __fadd_rn(s, __fmul_rn(ev[i].x, ev[i].x));
                s = __fadd_rn(s, __fmul_rn(ev[i].y, ev[i].y));
                s = __fadd_rn(s, __fmul_rn(ev[i].z, ev[i].z));
                s = __fadd_rn(s, __fmul_rn(ev[i].w, ev[i].w));
            }
            unsigned pw[16];
#pragma unroll
            for (int pp = 0; pp < 16; ++pp) {
                int p = c * 16 + pp;
                int w = (p & ~7) + ((p >> 1) & 3) + 4 * (p & 1);
                float4 f = ev[(w >> 1) - c * 8];
                float lo = (w & 1) ? f.z : f.x;
                float hi = (w & 1) ? f.w : f.y;
                __half2 b = __float22half2_rn(make_float2(lo, hi));
                pw[pp] = *(unsigned*)&b;
            }
            uint4* d4 = (uint4*)(bsw + tid * 40) + c * 4;
#pragma unroll
            for (int i = 0; i < 4; ++i) d4[i] = make_uint4(pw[4 * i], pw[4 * i + 1], pw[4 * i + 2], pw[4 * i + 3]);
        }
        eef[tid] = s;
        eeh[tid] = __float2half_rn(s);
    }
    const unsigned* eeh2 = (const unsigned*)eeh;

    // ================ persistent loop over row-blocks ================
    for (int blk = blockIdx.x; blk < nblk; blk += GRID) {
        const size_t blockRow = (size_t)blk * ROWS_CTA;
        __syncthreads();                         // prior block fully consumed
        if (tid < 16) { qcnt[tid] = 0; wflg[tid] = 0; }
        minr[tid] = ~0ull;

        // ---- prolog A: z row -> exact zz + f16(-2z), chunked ----
        {
            const float4* zr = (const float4*)(z + (blockRow + tid) * Dm);
            float zz = 0.0f;
#pragma unroll
            for (int c = 0; c < 2; ++c) {
                float4 v[8];
#pragma unroll
                for (int i = 0; i < 8; ++i) v[i] = zr[c * 8 + i];
#pragma unroll
                for (int i = 0; i < 8; ++i) {
                    zz = __fadd_rn(zz, __fmul_rn(v[i].x, v[i].x));
                    zz = __fadd_rn(zz, __fmul_rn(v[i].y, v[i].y));
                    zz = __fadd_rn(zz, __fmul_rn(v[i].z, v[i].z));
                    zz = __fadd_rn(zz, __fmul_rn(v[i].w, v[i].w));
                }
                unsigned p[16];
#pragma unroll
                for (int i = 0; i < 8; ++i) {
                    __half2 b0 = __float22half2_rn(make_float2(-2.f * v[i].x, -2.f * v[i].y));
                    __half2 b1 = __float22half2_rn(make_float2(-2.f * v[i].z, -2.f * v[i].w));
                    p[2 * i] = *(unsigned*)&b0;
                    p[2 * i + 1] = *(unsigned*)&b1;
                }
                uint4* d4 = (uint4*)(zhw + tid * 36) + c * 4;
#pragma unroll
                for (int i = 0; i < 4; ++i) d4[i] = make_uint4(p[4 * i], p[4 * i + 1], p[4 * i + 2], p[4 * i + 3]);
            }
            zzs[tid] = zz;
        }
        __syncthreads();

        // ---- A fragments: M=32 (rows ra, ra+8, ra+16, ra+24) ----
        const int ra = wid * 32 + rg;
        unsigned a[32];
#pragma unroll
        for (int b = 0; b < 2; ++b)
#pragma unroll
            for (int ks = 0; ks < 4; ++ks) {
                int rbase = (ra + 16 * b) * 36;
                a[b * 16 + ks * 4 + 0] = zhw[rbase + q + ks * 8];
                a[b * 16 + ks * 4 + 1] = zhw[rbase + 8 * 36 + q + ks * 8];
                a[b * 16 + ks * 4 + 2] = zhw[rbase + q + 4 + ks * 8];
                a[b * 16 + ks * 4 + 3] = zhw[rbase + 8 * 36 + q + 4 + ks * 8];
            }

        // ---- pass 1: fast mins (score = ee - 2 z.e, fp16) ----
        unsigned mm0 = 0x7BFF7BFFu, mm1 = 0x7BFF7BFFu, mm2 = 0x7BFF7BFFu, mm3 = 0x7BFF7BFFu;
#pragma unroll 2
        for (int t = 0; t < NTILES; ++t) {
            unsigned einit = eeh2[t * 4 + q];
            unsigned c01 = einit, c23 = einit, c45 = einit, c67 = einit;
            const unsigned* bp = bsw + (t * 8 + rg) * 40 + 2 * q;
#pragma unroll
            for (int ks = 0; ks < 4; ++ks) {
                uint2 b = *(const uint2*)(bp + ks * 8);
                mma16816h(c01, c23, a[ks * 4], a[ks * 4 + 1], a[ks * 4 + 2], a[ks * 4 + 3], b.x, b.y);
                mma16816h(c45, c67, a[16 + ks * 4], a[17 + ks * 4], a[18 + ks * 4], a[19 + ks * 4], b.x, b.y);
            }
            mm0 = hmin2u(mm0, c01);
            mm1 = hmin2u(mm1, c23);
            mm2 = hmin2u(mm2, c45);
            mm3 = hmin2u(mm3, c67);
            unsigned tw = hmin2u(hmin2u(c01, c23), hmin2u(c45, c67));
            __half2 th = *(__half2*)&tw;
            float tm = fminf(__low2float(th), __high2float(th));
            tm = fminf(tm, __shfl_xor_sync(0xffffffffu, tm, 1));
            tm = fminf(tm, __shfl_xor_sync(0xffffffffu, tm, 2));
            if (q == 0) tminp[(wid * NTILES + t) * 8 + rg] = __float2half(tm);
        }
        __syncwarp();

        __half2 h0 = *(__half2*)&mm0, h1 = *(__half2*)&mm1;
        __half2 h2 = *(__half2*)&mm2, h3 = *(__half2*)&mm3;
        float mr0 = fminf(__low2float(h0), __high2float(h0));
        float mr1 = fminf(__low2float(h1), __high2float(h1));
        float mr2 = fminf(__low2float(h2), __high2float(h2));
        float mr3 = fminf(__low2float(h3), __high2float(h3));
#pragma unroll
        for (int off = 1; off < 4; off <<= 1) {
            mr0 = fminf(mr0, __shfl_xor_sync(0xffffffffu, mr0, off));
            mr1 = fminf(mr1, __shfl_xor_sync(0xffffffffu, mr1, off));
            mr2 = fminf(mr2, __shfl_xor_sync(0xffffffffu, mr2, off));
            mr3 = fminf(mr3, __shfl_xor_sync(0xffffffffu, mr3, off));
        }
        const float t0 = mr0 + MARGIN, t1 = mr1 + MARGIN;
        const float t2 = mr2 + MARGIN, t3 = mr3 + MARGIN;
        const float thrq = fmaxf(fmaxf(t0, t1), fmaxf(t2, t3));

        // ---- pass 2: pruned recompute, enqueue candidates (call-free) ----
#define PUSH(rowv, jv) do {                                                       \
        unsigned pk_ = (unsigned)(rowv) | ((unsigned)(jv) << 9);                  \
        int qi_ = atomicAdd(qcnt + wid, 1);                                       \
        if (qi_ < QCAP) que[wid * QCAP + qi_] = pk_;                              \
        else wflg[wid] = 1;                                                       \
    } while (0)

#pragma unroll 1
        for (int t = 0; t < NTILES; ++t) {
            float tm = __half2float(tminp[(wid * NTILES + t) * 8 + rg]);
            if (!__any_sync(0xffffffffu, tm <= thrq)) continue;

            unsigned einit = eeh2[t * 4 + q];
            unsigned c01 = einit, c23 = einit, c45 = einit, c67 = einit;
            const unsigned* bp = bsw + (t * 8 + rg) * 40 + 2 * q;
#pragma unroll
            for (int ks = 0; ks < 4; ++ks) {
                uint2 b = *(const uint2*)(bp + ks * 8);
                mma16816h(c01, c23, a[ks * 4], a[ks * 4 + 1], a[ks * 4 + 2], a[ks * 4 + 3], b.x, b.y);
                mma16816h(c45, c67, a[16 + ks * 4], a[17 + ks * 4], a[18 + ks * 4], a[19 + ks * 4], b.x, b.y);
            }
            __half2 p0 = *(__half2*)&c01, p1 = *(__half2*)&c23;
            __half2 p2 = *(__half2*)&c45, p3 = *(__half2*)&c67;
            int jb = t * 8 + 2 * q;
            if (__low2float(p0) <= t0) PUSH(ra, jb);
            if (__high2float(p0) <= t0) PUSH(ra, jb + 1);
            if (__low2float(p1) <= t1) PUSH(ra + 8, jb);
            if (__high2float(p1) <= t1) PUSH(ra + 8, jb + 1);
            if (__low2float(p2) <= t2) PUSH(ra + 16, jb);
            if (__high2float(p2) <= t2) PUSH(ra + 16, jb + 1);
            if (__low2float(p3) <= t3) PUSH(ra + 24, jb);
            if (__high2float(p3) <= t3) PUSH(ra + 24, jb + 1);
        }
#undef PUSH

        // ---- drain: 32 lanes rescore distinct candidates ----
        __syncwarp();
        int n = *(volatile int*)(qcnt + wid);
        int ncap = n < QCAP ? n : QCAP;
        for (int base = 0; base < ncap; base += 32) {
            int k2 = base + lane;
            if (k2 < ncap) exact_commit(que[wid * QCAP + k2], z, cb, blockRow, zzs, eef, minr);
        }
        if (wflg[wid]) {
            // Unreachable in practice; provably-correct fallback: exhaustive
            // rescore of this warp's 32 rows against all codes.
            for (int rr = 0; rr < 32; ++rr) {
                int row = wid * 32 + rr;
                for (int j = lane; j < Kc; j += 32)
                    exact_commit((unsigned)row | ((unsigned)j << 9), z, cb, blockRow, zzs, eef, minr);
            }
        }
        __syncthreads();

        // ---- gather + write both tuple halves ----
#pragma unroll
        for (int it = 0; it < 2; ++it) {
            int row = (tid >> 1) + it * 256, hh = tid & 1;
            int j = (int)(unsigned)(minr[row] & 0xFFFFFFFFull);
            size_t g = blockRow + row;
            const float4* s4 = (const float4*)(cb + (size_t)j * Dm + hh * 32);
            float4* o1 = (float4*)(out + g * Dm + hh * 32);
            float4* o2 = (half > 0) ? (float4*)(out + half + g * Dm + hh * 32) : nullptr;
#pragma unroll
            for (int i = 0; i < 8; ++i) {
                float4 tv = s4[i];
                o1[i] = tv;
                if (o2) o2[i] = tv;
            }
        }
    }
}

extern "C" void kernel_launch(void* const* d_in, const int* in_sizes, int n_in,
                              void* d_out, int out_size) {
    const float* z = (const float*)d_in[0];
    const float* cb = (const float*)d_in[1];
    float* out = (float*)d_out;
    const int N = in_sizes[0] / Dm;                      // 131072
    const int nblk = N / ROWS_CTA;                       // 256
    long long half = ((long long)out_size >= 2LL * N * Dm) ? (long long)out_size / 2 : 0;

    cudaFuncSetAttribute(vq_kernel, cudaFuncAttributeMaxDynamicSharedMemorySize, SM_TOTAL);
    int grid = nblk < GRID ? nblk : GRID;
    vq_kernel<<<grid, THREADS, SM_TOTAL>>>(z, cb, out, half, nblk);
}